// round 1
// baseline (speedup 1.0000x reference)
#include <cuda_runtime.h>

// ---------------------------------------------------------------------------
// GraphConvLSTM on GB300 — Round 1: fp32 baseline, well-tiled.
//
// out[b, t, m, j] = h_t where per step:
//   msg = A_norm @ h_prev          (sparse, 22 nodes, cliques)
//   g   = msg @ gcn_w + gcn_b      ((B*N,128) @ (128,128) GEMM)
//   i,f,o = sigmoid(x{i,f,o} + g); c~ = tanh(xc + g)
//   c = f*c + i*c~ ; h = o*tanh(c)
// ---------------------------------------------------------------------------

#define BATCH   512
#define INDIM   256
#define HDIM    128
#define TSTEPS  100
#define NNODES  22
#define NROWS   (BATCH * NNODES)   // 11264

// -------------------- scratch (device globals, no allocs) ------------------
__device__ float g_xg[4 * BATCH * HDIM];        // precomputed gate inputs (4,B,H)
__device__ float g_h[2][NROWS * HDIM];          // ping-pong hidden state
__device__ float g_c[NROWS * HDIM];             // cell state

// -------------------- normalized adjacency (baked constants) ---------------
// cliques: [0,2,5,8,11] [0,1,4,7,10] [0,3,6,9,12,15] [9,14,17,19,21] [9,13,16,18,20]
// deg: node0=13, node9=13, nodes{3,6,12,15}=5, rest=4;  coef = dinv[m]*dinv[n]
__constant__ int c_cnt[NNODES] = {13,4,4,5,4,4,5,4,4,13,4,4,5,4,4,5,4,4,4,4,4,4};
__constant__ int c_nbr[NNODES][13] = {
    {1,2,3,4,5,6,7,8,9,10,11,12,15},        // 0
    {0,4,7,10, 0,0,0,0,0,0,0,0,0},          // 1
    {0,5,8,11, 0,0,0,0,0,0,0,0,0},          // 2
    {0,6,9,12,15, 0,0,0,0,0,0,0,0},         // 3
    {0,1,7,10, 0,0,0,0,0,0,0,0,0},          // 4
    {0,2,8,11, 0,0,0,0,0,0,0,0,0},          // 5
    {0,3,9,12,15, 0,0,0,0,0,0,0,0},         // 6
    {0,1,4,10, 0,0,0,0,0,0,0,0,0},          // 7
    {0,2,5,11, 0,0,0,0,0,0,0,0,0},          // 8
    {0,3,6,12,15,13,14,16,17,18,19,20,21},  // 9
    {0,1,4,7, 0,0,0,0,0,0,0,0,0},           // 10
    {0,2,5,8, 0,0,0,0,0,0,0,0,0},           // 11
    {0,3,6,9,15, 0,0,0,0,0,0,0,0},          // 12
    {9,16,18,20, 0,0,0,0,0,0,0,0,0},        // 13
    {9,17,19,21, 0,0,0,0,0,0,0,0,0},        // 14
    {0,3,6,9,12, 0,0,0,0,0,0,0,0},          // 15
    {9,13,18,20, 0,0,0,0,0,0,0,0,0},        // 16
    {9,14,19,21, 0,0,0,0,0,0,0,0,0},        // 17
    {9,13,16,20, 0,0,0,0,0,0,0,0,0},        // 18
    {9,14,17,21, 0,0,0,0,0,0,0,0,0},        // 19
    {9,13,16,18, 0,0,0,0,0,0,0,0,0},        // 20
    {9,14,17,19, 0,0,0,0,0,0,0,0,0}         // 21
};
__constant__ float c_dinv[NNODES] = {
    0.2773500979f, 0.5f, 0.5f, 0.4472135955f, 0.5f, 0.5f, 0.4472135955f, 0.5f, 0.5f,
    0.2773500979f, 0.5f, 0.5f, 0.4472135955f, 0.5f, 0.5f, 0.4472135955f,
    0.5f, 0.5f, 0.5f, 0.5f, 0.5f, 0.5f
};

// -------------------- math helpers (saturation-safe) ------------------------
__device__ __forceinline__ float fsig(float x) {
    // 1/(1+exp(-x)); exp->inf => 0, exp->0 => 1.  rel err ~1e-6.
    return __fdividef(1.0f, 1.0f + __expf(-x));
}
__device__ __forceinline__ float ftanh_(float x) {
    // tanh(x) = 1 - 2/(exp(2x)+1); exp->inf => 1, exp->0 => -1.
    return 1.0f - __fdividef(2.0f, __expf(2.0f * x) + 1.0f);
}
__device__ __forceinline__ void cell(float gg, float xiv, float xfv, float xov,
                                     float xcv, float cprev,
                                     float& cn, float& hn) {
    float it = fsig(xiv + gg);
    float ft = fsig(xfv + gg);
    float ot = fsig(xov + gg);
    float ct = ftanh_(xcv + gg);
    cn = ft * cprev + it * ct;
    hn = ot * ftanh_(cn);
}

// -------------------- init: zero h0 and c ----------------------------------
__global__ void init_kernel() {
    int i = blockIdx.x * blockDim.x + threadIdx.x;
    float4 z = make_float4(0.f, 0.f, 0.f, 0.f);
    if (i < NROWS * HDIM / 4) {
        reinterpret_cast<float4*>(g_h[0])[i] = z;
        reinterpret_cast<float4*>(g_c)[i]    = z;
    }
}

// -------------------- gate projection: xg[g] = x @ W_g^T + b_g -------------
// grid (B/16, 4 gates), 128 threads.  Each block: 16 batches x 128 outputs.
__global__ __launch_bounds__(128) void gate_kernel(
    const float* __restrict__ x,
    const float* __restrict__ wi, const float* __restrict__ bi,
    const float* __restrict__ wf, const float* __restrict__ bf,
    const float* __restrict__ wo, const float* __restrict__ bo,
    const float* __restrict__ wc, const float* __restrict__ bc)
{
    __shared__ float xs[16 * INDIM];     // 16 KB
    __shared__ float ws[32 * 129];       // 16.5 KB, padded transpose tile

    int tid  = threadIdx.x;
    int gate = blockIdx.y;
    const float* w    = (gate == 0) ? wi : (gate == 1) ? wf : (gate == 2) ? wo : wc;
    const float* bias = (gate == 0) ? bi : (gate == 1) ? bf : (gate == 2) ? bo : bc;
    int b0 = blockIdx.x * 16;

    for (int i = tid; i < 16 * INDIM; i += 128) xs[i] = x[b0 * INDIM + i];

    float acc[16];
#pragma unroll
    for (int bb = 0; bb < 16; bb++) acc[bb] = 0.f;

    for (int k0 = 0; k0 < INDIM; k0 += 32) {
        __syncthreads();
        // stage W[j=0..127][k0..k0+32) transposed with pad 129 (conflict-free)
        for (int i = tid; i < 128 * 32; i += 128) {
            int j = i >> 5, k = i & 31;
            ws[k * 129 + j] = w[j * INDIM + k0 + k];   // coalesced global read
        }
        __syncthreads();
#pragma unroll 8
        for (int k = 0; k < 32; k++) {
            float wv = ws[k * 129 + tid];
#pragma unroll
            for (int bb = 0; bb < 16; bb++)
                acc[bb] += xs[bb * INDIM + k0 + k] * wv;
        }
    }
    float bv = bias[tid];
#pragma unroll
    for (int bb = 0; bb < 16; bb++)
        g_xg[(gate * BATCH + b0 + bb) * HDIM + tid] = acc[bb] + bv;
}

// -------------------- one LSTM step -----------------------------------------
// grid: 704 blocks = 352 row-tiles (32 rows of B*N) x 2 col-tiles (64 of H).
// 128 threads: microtile 4 rows x 4 cols; W staged in two 64-k halves.
__global__ __launch_bounds__(128) void step_kernel(
    const float* __restrict__ gw,   // gcn_w (H,H) row-major [k][j]
    const float* __restrict__ gb,   // gcn_b (H)
    float* __restrict__ out, int t)
{
    __shared__ float ws[64 * 64];     // 16 KB   W k-half [kk][j]
    __shared__ float ms[32 * 132];    // 16.9 KB msg tile, stride 132 (pad)

    const float* hprev = g_h[t & 1];
    float*       hnext = g_h[(t + 1) & 1];

    int tid = threadIdx.x;
    int r0 = (blockIdx.x >> 1) * 32;
    int c0 = (blockIdx.x & 1) * 64;

    // ---- msg = A_norm @ h_prev for this 32-row x 128-col tile (float4) ----
#pragma unroll
    for (int p = 0; p < 8; p++) {
        int id  = p * 128 + tid;
        int row = id >> 5;               // one row per warp -> uniform m
        int jv  = (id & 31) << 2;        // float4 column
        int gr  = r0 + row;
        int b   = gr / NNODES;
        int m   = gr - b * NNODES;
        const float* hb = hprev + (size_t)b * (NNODES * HDIM);
        float4 a = make_float4(0.f, 0.f, 0.f, 0.f);
        int cnt  = c_cnt[m];
        float dm = c_dinv[m];
        for (int q = 0; q < cnt; q++) {
            int n = c_nbr[m][q];
            float cf = dm * c_dinv[n];
            float4 hv = *reinterpret_cast<const float4*>(hb + n * HDIM + jv);
            a.x += cf * hv.x; a.y += cf * hv.y;
            a.z += cf * hv.z; a.w += cf * hv.w;
        }
        *reinterpret_cast<float4*>(&ms[row * 132 + jv]) = a;  // aligned (132%4==0)
    }

    // ---- GEMM: acc[4][4] = msg_tile @ W_tile -------------------------------
    int cg = tid & 15;          // 16 col groups x 4 cols
    int rg = tid >> 4;          // 8 row groups x 4 rows
    float acc[4][4];
#pragma unroll
    for (int i = 0; i < 4; i++)
#pragma unroll
        for (int q = 0; q < 4; q++) acc[i][q] = 0.f;

    for (int khalf = 0; khalf < 2; khalf++) {
        __syncthreads();   // (iter0: msg+ws hazard; iter1: ws reuse hazard)
        for (int i = tid; i < 64 * 64; i += 128) {
            int kk = i >> 6, j = i & 63;
            ws[i] = gw[(khalf * 64 + kk) * HDIM + c0 + j];  // coalesced
        }
        __syncthreads();
#pragma unroll 4
        for (int kk = 0; kk < 64; kk++) {
            int k = khalf * 64 + kk;
            float4 w = *reinterpret_cast<const float4*>(&ws[kk * 64 + cg * 4]);
#pragma unroll
            for (int i = 0; i < 4; i++) {
                float mv = ms[(rg * 4 + i) * 132 + k];
                acc[i][0] += mv * w.x;
                acc[i][1] += mv * w.y;
                acc[i][2] += mv * w.z;
                acc[i][3] += mv * w.w;
            }
        }
    }

    // ---- LSTM epilogue ------------------------------------------------------
    int j = c0 + cg * 4;
    const float4 bias = *reinterpret_cast<const float4*>(gb + j);
#pragma unroll
    for (int i = 0; i < 4; i++) {
        int gr = r0 + rg * 4 + i;
        int b  = gr / NNODES;
        int m  = gr - b * NNODES;
        int go = b * HDIM + j;
        const float4 xi = *reinterpret_cast<const float4*>(g_xg + 0 * BATCH * HDIM + go);
        const float4 xf = *reinterpret_cast<const float4*>(g_xg + 1 * BATCH * HDIM + go);
        const float4 xo = *reinterpret_cast<const float4*>(g_xg + 2 * BATCH * HDIM + go);
        const float4 xc = *reinterpret_cast<const float4*>(g_xg + 3 * BATCH * HDIM + go);
        float4 cv = *reinterpret_cast<const float4*>(g_c + (size_t)gr * HDIM + j);

        float4 cn, hn;
        cell(acc[i][0] + bias.x, xi.x, xf.x, xo.x, xc.x, cv.x, cn.x, hn.x);
        cell(acc[i][1] + bias.y, xi.y, xf.y, xo.y, xc.y, cv.y, cn.y, hn.y);
        cell(acc[i][2] + bias.z, xi.z, xf.z, xo.z, xc.z, cv.z, cn.z, hn.z);
        cell(acc[i][3] + bias.w, xi.w, xf.w, xo.w, xc.w, cv.w, cn.w, hn.w);

        *reinterpret_cast<float4*>(g_c   + (size_t)gr * HDIM + j) = cn;
        *reinterpret_cast<float4*>(hnext + (size_t)gr * HDIM + j) = hn;
        size_t oidx = ((size_t)(b * TSTEPS + t) * NNODES + m) * HDIM + j;
        *reinterpret_cast<float4*>(out + oidx) = hn;
    }
}

// -------------------- launch -------------------------------------------------
extern "C" void kernel_launch(void* const* d_in, const int* in_sizes, int n_in,
                              void* d_out, int out_size) {
    (void)in_sizes; (void)n_in; (void)out_size;
    const float* x     = (const float*)d_in[0];
    const float* wi_w  = (const float*)d_in[1];
    const float* wi_b  = (const float*)d_in[2];
    const float* wf_w  = (const float*)d_in[3];
    const float* wf_b  = (const float*)d_in[4];
    const float* wo_w  = (const float*)d_in[5];
    const float* wo_b  = (const float*)d_in[6];
    const float* wc_w  = (const float*)d_in[7];
    const float* wc_b  = (const float*)d_in[8];
    const float* gcn_w = (const float*)d_in[9];
    const float* gcn_b = (const float*)d_in[10];
    float* out = (float*)d_out;

    init_kernel<<<(NROWS * HDIM / 4 + 255) / 256, 256>>>();
    gate_kernel<<<dim3(BATCH / 16, 4), 128>>>(x, wi_w, wi_b, wf_w, wf_b,
                                              wo_w, wo_b, wc_w, wc_b);
    for (int t = 0; t < TSTEPS; t++)
        step_kernel<<<(NROWS / 32) * 2, 128>>>(gcn_w, gcn_b, out, t);
}